// round 1
// baseline (speedup 1.0000x reference)
#include <cuda_runtime.h>

// ---------------------------------------------------------------------------
// VQ-VAE vector quantizer, GB300 sm_103a
//   z:  (32, 256, 32, 32) f32      -> z_flat (32768, 256), n = b*1024 + h*32 + w
//   E:  (1024, 256) f32
//   out layout (f32, concatenated reference returns):
//     [0, 8388608)              z_q_st  (B, D, H, W)
//     [8388608]                 commitment_loss
//     [8388609, 8421377)        indices (B, H, W) as float
//     [8421377, 8683521)        new_embedding (K, D)
//     [8683521, 8684545)        new_cs (K,)
//     [8684545, 8946689)        new_es (K, D)
// ---------------------------------------------------------------------------

#define N_ROWS   32768
#define K_CODES  1024
#define D_DIM    256

#define OFF_LOSS 8388608
#define OFF_IDX  8388609
#define OFF_EMB  8421377
#define OFF_CS   8683521
#define OFF_ES   8684545

__device__ float g_enorm[K_CODES];
__device__ int   g_indices[N_ROWS];
__device__ float g_counts[K_CODES];
__device__ float g_embed_sum[K_CODES * D_DIM];
__device__ float g_cluster[K_CODES];

// ---- packed f32x2 helpers (FFMA2 only reachable via PTX) ------------------
__device__ __forceinline__ void ffma2(unsigned long long &acc,
                                      unsigned long long a,
                                      unsigned long long b) {
    asm("fma.rn.f32x2 %0, %1, %2, %0;" : "+l"(acc) : "l"(a), "l"(b));
}
__device__ __forceinline__ unsigned long long pk(float lo, float hi) {
    unsigned long long r;
    asm("mov.b64 %0, {%1, %2};" : "=l"(r) : "f"(lo), "f"(hi));
    return r;
}
__device__ __forceinline__ float2 unpk(unsigned long long v) {
    float2 r;
    asm("mov.b64 {%0, %1}, %2;" : "=f"(r.x), "=f"(r.y) : "l"(v));
    return r;
}

// ---------------------------------------------------------------------------
// Kernel 1: per-code ||e||^2, zero scratch, zero loss slot
// ---------------------------------------------------------------------------
__global__ void k_init(const float* __restrict__ E, float* __restrict__ out) {
    const int k = blockIdx.x;
    const int t = threadIdx.x;
    float v = E[k * D_DIM + t];
    float s = v * v;
    #pragma unroll
    for (int o = 16; o; o >>= 1) s += __shfl_down_sync(0xffffffffu, s, o);
    __shared__ float ws[8];
    if ((t & 31) == 0) ws[t >> 5] = s;
    __syncthreads();
    if (t == 0) {
        float tot = 0.f;
        #pragma unroll
        for (int i = 0; i < 8; ++i) tot += ws[i];
        g_enorm[k]  = tot;
        g_counts[k] = 0.f;
        if (k == 0) out[OFF_LOSS] = 0.f;
    }
    g_embed_sum[k * D_DIM + t] = 0.f;
}

// ---------------------------------------------------------------------------
// Kernel 2: distance GEMM + argmin.
// Block: 64 z-rows x all 1024 codes.  128 threads, each 8 rows x 4 codes.
// A (64x256 f32) resident in smem; B tiles (64 codes x 32 dims) double-buffered
// with register prefetch; packed f32x2 FMA.
// dist = fl(fl(znorm - 2*dot) + enorm)  -- fp32 rounding matches reference.
// ---------------------------------------------------------------------------
__global__ __launch_bounds__(128)
void k_assign(const float* __restrict__ z, const float* __restrict__ E,
              float* __restrict__ out) {
    extern __shared__ float sm[];
    float* As = sm;                    // 16384 floats  (As[d][row], row-stride 64)
    float* Bs = sm + 16384;            // 2 * 32*68 = 4352 floats (Bs[d][k], stride 68)
    float* Zn = sm + 16384 + 4352;     // 64 floats

    const int t   = threadIdx.x;
    const int n0  = blockIdx.x * 64;
    const int b   = n0 >> 10;
    const int rem = n0 & 1023;

    const float4* zb4 = (const float4*)(z + (size_t)b * 262144 + rem);
    float4* As4 = (float4*)As;

    // ---- load A tile (coalesced: 64 contiguous floats per d) ----
    #pragma unroll
    for (int i = 0; i < 32; ++i) {
        int f = t + i * 128;
        As4[f] = zb4[(f >> 4) * 256 + (f & 15)];
    }
    __syncthreads();

    // ---- per-row ||z||^2, accumulated in double, rounded once to f32 ----
    if (t < 64) {
        double acc = 0.0;
        for (int d = 0; d < 256; ++d) {
            float v = As[d * 64 + t];
            acc += (double)v * (double)v;
        }
        Zn[t] = (float)acc;
    }
    __syncthreads();

    const int tx = t & 15;     // code group: codes tx*4 .. tx*4+3 per tile
    const int ty = t >> 4;     // row group: rows ty*8 .. ty*8+7
    const float4* E4  = (const float4*)E;
    const float4* gn4 = (const float4*)g_enorm;

    float bestd[8];
    int   besti[8];
    float znr[8];
    #pragma unroll
    for (int r = 0; r < 8; ++r) {
        bestd[r] = 3.4e38f; besti[r] = 0;
        znr[r] = Zn[ty * 8 + r];
    }

    // prefetch first B chunk (kt=0, dc=0)
    float4 pre[4];
    #pragma unroll
    for (int i = 0; i < 4; ++i) {
        int f = t + i * 128;
        pre[i] = E4[(size_t)(f >> 3) * 64 + (f & 7)];
    }

    unsigned long long acc[8][2];
    float4 en4 = make_float4(0.f, 0.f, 0.f, 0.f);

    for (int ch = 0; ch < 128; ++ch) {            // 16 k-tiles x 8 d-chunks
        const int kt  = ch >> 3;
        const int dcx = ch & 7;
        const int dc  = dcx << 5;
        float* Bsb = Bs + (ch & 1) * 2176;

        if (dcx == 0) {
            #pragma unroll
            for (int r = 0; r < 8; ++r) { acc[r][0] = 0ull; acc[r][1] = 0ull; }
            en4 = gn4[kt * 16 + tx];
        }

        // store prefetched chunk transposed into smem
        #pragma unroll
        for (int i = 0; i < 4; ++i) {
            int f = t + i * 128;
            int k = f >> 3, j = f & 7;
            Bsb[(j * 4 + 0) * 68 + k] = pre[i].x;
            Bsb[(j * 4 + 1) * 68 + k] = pre[i].y;
            Bsb[(j * 4 + 2) * 68 + k] = pre[i].z;
            Bsb[(j * 4 + 3) * 68 + k] = pre[i].w;
        }
        __syncthreads();

        // prefetch next chunk while computing this one
        if (ch + 1 < 128) {
            const int ktn = (ch + 1) >> 3;
            const int dcn = ((ch + 1) & 7) << 5;
            #pragma unroll
            for (int i = 0; i < 4; ++i) {
                int f = t + i * 128;
                int k = f >> 3, j = f & 7;
                pre[i] = E4[(size_t)(ktn * 64 + k) * 64 + (dcn >> 2) + j];
            }
        }

        const float4* Bs4 = (const float4*)Bsb;
        #pragma unroll 4
        for (int d = 0; d < 32; ++d) {
            float4 a0 = As4[(dc + d) * 16 + ty * 2];
            float4 a1 = As4[(dc + d) * 16 + ty * 2 + 1];
            float4 bv = Bs4[d * 17 + tx];
            unsigned long long blo = pk(bv.x, bv.y);
            unsigned long long bhi = pk(bv.z, bv.w);
            float av[8] = {a0.x, a0.y, a0.z, a0.w, a1.x, a1.y, a1.z, a1.w};
            #pragma unroll
            for (int r = 0; r < 8; ++r) {
                unsigned long long aa = pk(av[r], av[r]);
                ffma2(acc[r][0], aa, blo);
                ffma2(acc[r][1], aa, bhi);
            }
        }
        __syncthreads();

        if (dcx == 7) {
            const int kb = kt * 64 + tx * 4;
            #pragma unroll
            for (int r = 0; r < 8; ++r) {
                float2 p0 = unpk(acc[r][0]);
                float2 p1 = unpk(acc[r][1]);
                float zn = znr[r];
                float di;
                di = (zn - 2.0f * p0.x) + en4.x;
                if (di < bestd[r]) { bestd[r] = di; besti[r] = kb + 0; }
                di = (zn - 2.0f * p0.y) + en4.y;
                if (di < bestd[r]) { bestd[r] = di; besti[r] = kb + 1; }
                di = (zn - 2.0f * p1.x) + en4.z;
                if (di < bestd[r]) { bestd[r] = di; besti[r] = kb + 2; }
                di = (zn - 2.0f * p1.y) + en4.w;
                if (di < bestd[r]) { bestd[r] = di; besti[r] = kb + 3; }
            }
        }
    }

    // ---- cross-thread argmin reduce (16 tx per row), first-index tie-break ----
    float* Ss = Bs;                  // reuse B buffer (loop is done, all synced)
    int*   Si = (int*)(Bs + 1024);
    #pragma unroll
    for (int r = 0; r < 8; ++r) {
        int row = ty * 8 + r;
        Ss[row * 16 + tx] = bestd[r];
        Si[row * 16 + tx] = besti[r];
    }
    __syncthreads();
    if (t < 64) {
        float bd = Ss[t * 16];
        int   bi = Si[t * 16];
        #pragma unroll
        for (int j = 1; j < 16; ++j) {
            float d2 = Ss[t * 16 + j];
            int   i2 = Si[t * 16 + j];
            if (d2 < bd || (d2 == bd && i2 < bi)) { bd = d2; bi = i2; }
        }
        int n = n0 + t;
        g_indices[n] = bi;
        out[(size_t)OFF_IDX + n] = (float)bi;
        atomicAdd(&g_counts[bi], 1.0f);
    }
}

// ---------------------------------------------------------------------------
// Kernel 3: gather z_q (straight-through), commitment loss, scatter embed_sum
// ---------------------------------------------------------------------------
__global__ void k_gather(const float* __restrict__ z, const float* __restrict__ E,
                         float* __restrict__ out) {
    __shared__ int sidx[64];
    __shared__ float ws[8];
    const int t   = threadIdx.x;   // 256
    const int n0  = blockIdx.x * 64;
    const int b   = n0 >> 10;
    const int rem = n0 & 1023;
    const float* zb = z   + (size_t)b * 262144 + rem;
    float*       qb = out + (size_t)b * 262144 + rem;

    if (t < 64) sidx[t] = g_indices[n0 + t];
    __syncthreads();

    float lsum = 0.f;
    #pragma unroll 4
    for (int it = 0; it < 32; ++it) {
        int f  = t + it * 256;
        int d2 = f >> 6, nl = f & 63;
        int d  = d2 << 1;
        int idx = sidx[nl];
        float z0 = zb[d * 1024 + nl];
        float z1 = zb[d * 1024 + 1024 + nl];
        float2 e = *(const float2*)(E + (size_t)idx * 256 + d);
        qb[d * 1024 + nl]        = z0 + (e.x - z0);   // straight-through value
        qb[d * 1024 + 1024 + nl] = z1 + (e.y - z1);
        float f0 = z0 - e.x, f1 = z1 - e.y;
        lsum += f0 * f0 + f1 * f1;
        atomicAdd((float2*)(g_embed_sum + (size_t)idx * 256 + d),
                  make_float2(z0, z1));
    }
    #pragma unroll
    for (int o = 16; o; o >>= 1) lsum += __shfl_down_sync(0xffffffffu, lsum, o);
    if ((t & 31) == 0) ws[t >> 5] = lsum;
    __syncthreads();
    if (t == 0) {
        float tot = 0.f;
        #pragma unroll
        for (int i = 0; i < 8; ++i) tot += ws[i];
        atomicAdd(out + OFF_LOSS, tot * (1.0f / 8388608.0f));
    }
}

// ---------------------------------------------------------------------------
// Kernel 4: EMA cluster size + cluster normalizer
// ---------------------------------------------------------------------------
__global__ void k_cs(const float* __restrict__ cs_in, float* __restrict__ out) {
    const int t = threadIdx.x;   // 1024
    float c = 0.99f * cs_in[t] + 0.01f * g_counts[t];
    out[(size_t)OFF_CS + t] = c;

    __shared__ float ws[32];
    __shared__ float n_tot;
    float s = c;
    #pragma unroll
    for (int o = 16; o; o >>= 1) s += __shfl_down_sync(0xffffffffu, s, o);
    if ((t & 31) == 0) ws[t >> 5] = s;
    __syncthreads();
    if (t == 0) {
        float tot = 0.f;
        #pragma unroll
        for (int i = 0; i < 32; ++i) tot += ws[i];
        n_tot = tot;
    }
    __syncthreads();
    float n  = n_tot;
    float cl = (c + 1e-5f) / (n + 1024.0f * 1e-5f) * n;
    g_cluster[t] = cl;
}

// ---------------------------------------------------------------------------
// Kernel 5: EMA embed sum + normalized codebook
// ---------------------------------------------------------------------------
__global__ void k_emb(const float* __restrict__ es_in, float* __restrict__ out) {
    const int i = blockIdx.x * 1024 + threadIdx.x;   // grid 256 -> 262144
    float es = 0.99f * es_in[i] + 0.01f * g_embed_sum[i];
    out[(size_t)OFF_ES  + i] = es;
    out[(size_t)OFF_EMB + i] = es / g_cluster[i >> 8];
}

// ---------------------------------------------------------------------------
extern "C" void kernel_launch(void* const* d_in, const int* in_sizes, int n_in,
                              void* d_out, int out_size) {
    const float* z  = (const float*)d_in[0];
    const float* E  = (const float*)d_in[1];
    const float* cs = (const float*)d_in[2];
    const float* es = (const float*)d_in[3];
    float* out = (float*)d_out;

    cudaFuncSetAttribute(k_assign, cudaFuncAttributeMaxDynamicSharedMemorySize,
                         83200);

    k_init  <<<1024, 256>>>(E, out);
    k_assign<<< 512, 128, 83200>>>(z, E, out);
    k_gather<<< 512, 256>>>(z, E, out);
    k_cs    <<<   1, 1024>>>(cs, out);
    k_emb   <<< 256, 1024>>>(es, out);
}

// round 4
// speedup vs baseline: 1.1380x; 1.1380x over previous
#include <cuda_runtime.h>
#include <cuda_fp16.h>
#include <cstdint>

// ---------------------------------------------------------------------------
// VQ-VAE vector quantizer, GB300 sm_103a (compiled as sm_103-generic).
// Tensor-core (mma.sync fp16) approximate assign + exact fp32 rescue.
//   z:  (32, 256, 32, 32) f32   -> rows n = b*1024 + h*32 + w, D=256
//   E:  (1024, 256) f32
//   out (f32): [0,8388608) z_q_st | [8388608] loss | [8388609,+32768) idx |
//              [8421377,+262144) new_emb | [8683521,+1024) new_cs |
//              [8684545,+262144) new_es
// ---------------------------------------------------------------------------

#define N_ROWS   32768
#define K_CODES  1024
#define D_DIM    256

#define OFF_LOSS 8388608
#define OFF_IDX  8388609
#define OFF_EMB  8421377
#define OFF_CS   8683521
#define OFF_ES   8684545

// |approx_score - ref_score| <= 2*2^-10*Sum|z_i e_i| (<=3.6e-4) + ref fp32
// rounding (~1.2e-4). Pairwise < 8.4e-4 worst case -> theta = 1e-3 is safe.
#define THETA    1e-3f

__device__ float   g_enorm[K_CODES];
__device__ int     g_indices[N_ROWS];
__device__ float   g_counts[K_CODES];
__device__ float   g_embed_sum[K_CODES * D_DIM];
__device__ float   g_cluster[K_CODES];
__device__ __half  g_E16[K_CODES * D_DIM];
__device__ int     g_contested[N_ROWS];
__device__ int     g_nc;

// ---------------- helpers --------------------------------------------------
__device__ __forceinline__ uint32_t smem_to_u32(const void* p) {
    uint32_t a;
    asm("{ .reg .u64 t; cvta.to.shared.u64 t, %1; cvt.u32.u64 %0, t; }"
        : "=r"(a) : "l"(p));
    return a;
}

__device__ __forceinline__ void ldm4(uint32_t r[4], uint32_t addr) {
    asm volatile("ldmatrix.sync.aligned.m8n8.x4.shared.b16 {%0,%1,%2,%3}, [%4];"
                 : "=r"(r[0]), "=r"(r[1]), "=r"(r[2]), "=r"(r[3]) : "r"(addr));
}

__device__ __forceinline__ void mma16816(float c[4], const uint32_t a[4],
                                         uint32_t b0, uint32_t b1) {
    asm volatile(
        "mma.sync.aligned.m16n8k16.row.col.f32.f16.f16.f32 "
        "{%0,%1,%2,%3}, {%4,%5,%6,%7}, {%8,%9}, {%0,%1,%2,%3};"
        : "+f"(c[0]), "+f"(c[1]), "+f"(c[2]), "+f"(c[3])
        : "r"(a[0]), "r"(a[1]), "r"(a[2]), "r"(a[3]), "r"(b0), "r"(b1));
}

// ---- packed f32x2 helpers (exact-rescue path) -----------------------------
__device__ __forceinline__ void ffma2(unsigned long long &acc,
                                      unsigned long long a,
                                      unsigned long long b) {
    asm("fma.rn.f32x2 %0, %1, %2, %0;" : "+l"(acc) : "l"(a), "l"(b));
}
__device__ __forceinline__ unsigned long long pk(float lo, float hi) {
    unsigned long long r;
    asm("mov.b64 %0, {%1, %2};" : "=l"(r) : "f"(lo), "f"(hi));
    return r;
}
__device__ __forceinline__ float2 unpk(unsigned long long v) {
    float2 r;
    asm("mov.b64 {%0, %1}, %2;" : "=f"(r.x), "=f"(r.y) : "l"(v));
    return r;
}

// ---------------------------------------------------------------------------
// Kernel 1: ||e||^2, E -> fp16, zero scratch
// ---------------------------------------------------------------------------
__global__ void k_init(const float* __restrict__ E, float* __restrict__ out) {
    const int k = blockIdx.x;
    const int t = threadIdx.x;
    float v = E[k * D_DIM + t];
    g_E16[k * D_DIM + t] = __float2half_rn(v);
    float s = v * v;
    #pragma unroll
    for (int o = 16; o; o >>= 1) s += __shfl_down_sync(0xffffffffu, s, o);
    __shared__ float ws[8];
    if ((t & 31) == 0) ws[t >> 5] = s;
    __syncthreads();
    if (t == 0) {
        float tot = 0.f;
        #pragma unroll
        for (int i = 0; i < 8; ++i) tot += ws[i];
        g_enorm[k]  = tot;
        g_counts[k] = 0.f;
        if (k == 0) { out[OFF_LOSS] = 0.f; g_nc = 0; }
    }
    g_embed_sum[k * D_DIM + t] = 0.f;
}

// ---------------------------------------------------------------------------
// Kernel 2: fp16 mma.sync GEMM (128 rows/CTA x 1024 codes, D=256) + argmin.
// 8 warps: 4(m) x 2(n). Warp tile 32 x 64. 8 code-chunks of 128, B chunks
// double-buffered via cp.async. score(k) = enorm[k] - 2*dot.
// Swizzle: byte_off = row*512 + d*2, XOR ((row&7)<<4) -> conflict-free LDSM.
// ---------------------------------------------------------------------------
#define SM_A     0
#define SM_B     65536
#define SM_EN    196608
#define SM_RED_B 200704
#define SM_RED_S 204800
#define SM_RED_I 208896
#define SMEM_MMA_TOTAL 212992

__global__ __launch_bounds__(256, 1)
void k_mma(const float* __restrict__ z, float* __restrict__ out) {
    extern __shared__ char smem[];
    const uint32_t sb = smem_to_u32(smem);
    const int tid  = threadIdx.x;
    const int warp = tid >> 5;
    const int lane = tid & 31;
    const int n0  = blockIdx.x * 128;
    const int b   = n0 >> 10;
    const int hw0 = n0 & 1023;

    // ---- prologue: A tile (z rows -> fp16, swizzled row-major [row][d]) ----
    const float4* zb4 = (const float4*)(z + (size_t)b * 262144 + hw0);
    #pragma unroll 4
    for (int i = 0; i < 32; ++i) {
        int f  = i * 256 + tid;
        int d  = f >> 5;
        int r4 = f & 31;
        float4 v = zb4[d * 256 + r4];
        float vv[4] = {v.x, v.y, v.z, v.w};
        #pragma unroll
        for (int j = 0; j < 4; ++j) {
            int row = r4 * 4 + j;
            uint32_t off = ((uint32_t)row << 9) | ((uint32_t)d << 1);
            off ^= (uint32_t)(row & 7) << 4;
            *(__half*)(smem + off) = __float2half_rn(vv[j]);
        }
    }
    float* s_en = (float*)(smem + SM_EN);
    #pragma unroll
    for (int i = 0; i < 4; ++i) s_en[tid + i * 256] = g_enorm[tid + i * 256];

    // ---- cp.async B chunk issue (chunk c -> buf c&1) ----
    auto issue = [&](int c) {
        const __half* src = g_E16 + (size_t)c * 128 * 256;
        const uint32_t base = sb + SM_B + (uint32_t)(c & 1) * 65536;
        #pragma unroll
        for (int i = 0; i < 16; ++i) {
            int lin  = tid + i * 256;
            int code = lin >> 5, d8 = lin & 31;
            uint32_t off = ((uint32_t)code << 9) + ((uint32_t)d8 << 4);
            off ^= (uint32_t)(code & 7) << 4;
            const void* g = src + code * 256 + d8 * 8;
            asm volatile("cp.async.cg.shared.global [%0], [%1], 16;"
                         :: "r"(base + off), "l"(g));
        }
        asm volatile("cp.async.commit_group;" ::: "memory");
    };
    issue(0);
    issue(1);
    __syncthreads();   // A + s_en visible

    // ---- per-lane ldmatrix address precompute ----
    const int mw = warp & 3;        // m-tile group (rows mw*32..)
    const int nc = warp >> 2;       // n half (codes nc*64..)
    const int mat = lane >> 3, rwi = lane & 7;

    uint32_t aBase[2], aXor[2];
    #pragma unroll
    for (int mt = 0; mt < 2; ++mt) {
        int row = mw * 32 + mt * 16 + rwi + ((mat & 1) << 3);
        aBase[mt] = sb + ((uint32_t)row << 9);
        aXor[mt]  = (uint32_t)(row & 7) << 4;
    }
    const uint32_t aK = (uint32_t)(mat >> 1) << 4;

    uint32_t bBase[4], bXor[4];
    #pragma unroll
    for (int np = 0; np < 4; ++np) {
        int code = nc * 64 + np * 16 + rwi + ((mat >> 1) << 3);
        bBase[np] = ((uint32_t)code << 9);
        bXor[np]  = (uint32_t)(code & 7) << 4;
    }
    const uint32_t bK = (uint32_t)(mat & 1) << 4;

    float bb[4], ss[4];
    int   ii[4];
    #pragma unroll
    for (int l = 0; l < 4; ++l) { bb[l] = 3.4e38f; ss[l] = 3.4e38f; ii[l] = 0; }

    for (int c = 0; c < 8; ++c) {
        if (c == 7) asm volatile("cp.async.wait_group 0;" ::: "memory");
        else        asm volatile("cp.async.wait_group 1;" ::: "memory");
        __syncthreads();

        const uint32_t bBuf = sb + SM_B + (uint32_t)(c & 1) * 65536;
        float acc[2][8][4];
        #pragma unroll
        for (int mt = 0; mt < 2; ++mt)
            #pragma unroll
            for (int nt = 0; nt < 8; ++nt)
                #pragma unroll
                for (int q = 0; q < 4; ++q) acc[mt][nt][q] = 0.f;

        #pragma unroll 2
        for (int ks = 0; ks < 16; ++ks) {
            const uint32_t kb = (uint32_t)ks << 5;
            uint32_t af[2][4], bf[4][4];
            #pragma unroll
            for (int mt = 0; mt < 2; ++mt)
                ldm4(af[mt], aBase[mt] + ((kb + aK) ^ aXor[mt]));
            #pragma unroll
            for (int np = 0; np < 4; ++np)
                ldm4(bf[np], bBuf + bBase[np] + ((kb + bK) ^ bXor[np]));
            #pragma unroll
            for (int mt = 0; mt < 2; ++mt)
                #pragma unroll
                for (int np = 0; np < 4; ++np) {
                    mma16816(acc[mt][np * 2],     af[mt], bf[np][0], bf[np][1]);
                    mma16816(acc[mt][np * 2 + 1], af[mt], bf[np][2], bf[np][3]);
                }
        }

        // fold scores: sc = enorm - 2*dot
        #pragma unroll
        for (int mt = 0; mt < 2; ++mt)
            #pragma unroll
            for (int nt = 0; nt < 8; ++nt) {
                int code = c * 128 + nc * 64 + nt * 8 + (lane & 3) * 2;
                float en0 = s_en[code], en1 = s_en[code + 1];
                int l0 = mt * 2, l1 = mt * 2 + 1;
                float sc;
                sc = fmaf(-2.0f, acc[mt][nt][0], en0);
                if (sc < bb[l0]) { ss[l0] = bb[l0]; bb[l0] = sc; ii[l0] = code; }
                else if (sc < ss[l0]) ss[l0] = sc;
                sc = fmaf(-2.0f, acc[mt][nt][1], en1);
                if (sc < bb[l0]) { ss[l0] = bb[l0]; bb[l0] = sc; ii[l0] = code + 1; }
                else if (sc < ss[l0]) ss[l0] = sc;
                sc = fmaf(-2.0f, acc[mt][nt][2], en0);
                if (sc < bb[l1]) { ss[l1] = bb[l1]; bb[l1] = sc; ii[l1] = code; }
                else if (sc < ss[l1]) ss[l1] = sc;
                sc = fmaf(-2.0f, acc[mt][nt][3], en1);
                if (sc < bb[l1]) { ss[l1] = bb[l1]; bb[l1] = sc; ii[l1] = code + 1; }
                else if (sc < ss[l1]) ss[l1] = sc;
            }

        __syncthreads();
        if (c + 2 < 8) issue(c + 2);
    }

    // ---- cross-thread reduce: 8 partials per row ----
    float* red_b = (float*)(smem + SM_RED_B);
    float* red_s = (float*)(smem + SM_RED_S);
    int*   red_i = (int*)  (smem + SM_RED_I);
    const int slot = nc * 4 + (lane & 3);
    #pragma unroll
    for (int l = 0; l < 4; ++l) {
        int R = mw * 32 + (l >> 1) * 16 + (l & 1) * 8 + (lane >> 2);
        red_b[R * 8 + slot] = bb[l];
        red_s[R * 8 + slot] = ss[l];
        red_i[R * 8 + slot] = ii[l];
    }
    __syncthreads();
    if (tid < 128) {
        float best = 3.4e38f, sec = 3.4e38f;
        int bi = 0;
        #pragma unroll
        for (int s = 0; s < 8; ++s) {
            float b2 = red_b[tid * 8 + s];
            float s2 = red_s[tid * 8 + s];
            int   i2 = red_i[tid * 8 + s];
            if (b2 < best) {
                sec = fminf(best, s2);
                best = b2; bi = i2;
            } else {
                sec = fminf(sec, b2);
            }
        }
        const int n = n0 + tid;
        g_indices[n] = bi;
        out[(size_t)OFF_IDX + n] = (float)bi;
        if (sec - best < THETA) {
            int p = atomicAdd(&g_nc, 1);
            g_contested[p] = n;
        }
    }
}

// ---------------------------------------------------------------------------
// Kernel 3: exact rescue — gathered contested rows, fp32 FFMA2, emulating
// the reference's fp32 rounding: dist = fl(fl(znorm - 2*dot) + enorm),
// znorm in double rounded once, strict-< argmin, index tie-break.
// ---------------------------------------------------------------------------
__global__ __launch_bounds__(128)
void k_exact(const float* __restrict__ z, const float* __restrict__ E,
             float* __restrict__ out) {
    extern __shared__ float sm[];
    float* As = sm;                      // 16384 floats
    float* Bs = sm + 16384;              // 4352 floats
    float* Zn = sm + 16384 + 4352;       // 64 floats
    int*   s_n = (int*)(sm + 20800);     // 64 ints

    const int cnt = g_nc;
    const int t = threadIdx.x;

    for (int tile = blockIdx.x; tile * 64 < cnt; tile += gridDim.x) {
        if (t < 64) {
            int i = tile * 64 + t;
            s_n[t] = (i < cnt) ? g_contested[i] : g_contested[0];
        }
        __syncthreads();

        for (int f = t; f < 16384; f += 128) {
            int d = f >> 6, r = f & 63;
            int n = s_n[r];
            As[d * 64 + r] =
                z[(size_t)(n >> 10) * 262144 + (size_t)d * 1024 + (n & 1023)];
        }
        __syncthreads();

        if (t < 64) {
            double acc = 0.0;
            for (int d = 0; d < 256; ++d) {
                float v = As[d * 64 + t];
                acc += (double)v * (double)v;
            }
            Zn[t] = (float)acc;
        }
        __syncthreads();

        const int tx = t & 15;
        const int ty = t >> 4;
        const float4* As4 = (const float4*)As;
        const float4* E4  = (const float4*)E;
        const float4* gn4 = (const float4*)g_enorm;

        float bestd[8]; int besti[8]; float znr[8];
        #pragma unroll
        for (int r = 0; r < 8; ++r) {
            bestd[r] = 3.4e38f; besti[r] = 0;
            znr[r] = Zn[ty * 8 + r];
        }

        float4 pre[4];
        #pragma unroll
        for (int i = 0; i < 4; ++i) {
            int f = t + i * 128;
            pre[i] = E4[(size_t)(f >> 3) * 64 + (f & 7)];
        }

        unsigned long long acc[8][2];
        float4 en4 = make_float4(0.f, 0.f, 0.f, 0.f);

        for (int ch = 0; ch < 128; ++ch) {
            const int kt  = ch >> 3;
            const int dcx = ch & 7;
            const int dc  = dcx << 5;
            float* Bsb = Bs + (ch & 1) * 2176;

            if (dcx == 0) {
                #pragma unroll
                for (int r = 0; r < 8; ++r) { acc[r][0] = 0ull; acc[r][1] = 0ull; }
                en4 = gn4[kt * 16 + tx];
            }
            #pragma unroll
            for (int i = 0; i < 4; ++i) {
                int f = t + i * 128;
                int k = f >> 3, j = f & 7;
                Bsb[(j * 4 + 0) * 68 + k] = pre[i].x;
                Bsb[(j * 4 + 1) * 68 + k] = pre[i].y;
                Bsb[(j * 4 + 2) * 68 + k] = pre[i].z;
                Bsb[(j * 4 + 3) * 68 + k] = pre[i].w;
            }
            __syncthreads();
            if (ch + 1 < 128) {
                const int ktn = (ch + 1) >> 3;
                const int dcn = ((ch + 1) & 7) << 5;
                #pragma unroll
                for (int i = 0; i < 4; ++i) {
                    int f = t + i * 128;
                    int k = f >> 3, j = f & 7;
                    pre[i] = E4[(size_t)(ktn * 64 + k) * 64 + (dcn >> 2) + j];
                }
            }
            const float4* Bs4 = (const float4*)Bsb;
            #pragma unroll 4
            for (int d = 0; d < 32; ++d) {
                float4 a0 = As4[(dc + d) * 16 + ty * 2];
                float4 a1 = As4[(dc + d) * 16 + ty * 2 + 1];
                float4 bv = Bs4[d * 17 + tx];
                unsigned long long blo = pk(bv.x, bv.y);
                unsigned long long bhi = pk(bv.z, bv.w);
                float av[8] = {a0.x, a0.y, a0.z, a0.w, a1.x, a1.y, a1.z, a1.w};
                #pragma unroll
                for (int r = 0; r < 8; ++r) {
                    unsigned long long aa = pk(av[r], av[r]);
                    ffma2(acc[r][0], aa, blo);
                    ffma2(acc[r][1], aa, bhi);
                }
            }
            __syncthreads();

            if (dcx == 7) {
                const int kb = kt * 64 + tx * 4;
                #pragma unroll
                for (int r = 0; r < 8; ++r) {
                    float2 p0 = unpk(acc[r][0]);
                    float2 p1 = unpk(acc[r][1]);
                    float zn = znr[r];
                    float di;
                    di = (zn - 2.0f * p0.x) + en4.x;
                    if (di < bestd[r]) { bestd[r] = di; besti[r] = kb + 0; }
                    di = (zn - 2.0f * p0.y) + en4.y;
                    if (di < bestd[r]) { bestd[r] = di; besti[r] = kb + 1; }
                    di = (zn - 2.0f * p1.x) + en4.z;
                    if (di < bestd[r]) { bestd[r] = di; besti[r] = kb + 2; }
                    di = (zn - 2.0f * p1.y) + en4.w;
                    if (di < bestd[r]) { bestd[r] = di; besti[r] = kb + 3; }
                }
            }
        }

        float* Ss = Bs;
        int*   Si = (int*)(Bs + 1024);
        #pragma unroll
        for (int r = 0; r < 8; ++r) {
            int row = ty * 8 + r;
            Ss[row * 16 + tx] = bestd[r];
            Si[row * 16 + tx] = besti[r];
        }
        __syncthreads();
        if (t < 64 && tile * 64 + t < cnt) {
            float bd = Ss[t * 16];
            int   bi = Si[t * 16];
            #pragma unroll
            for (int j = 1; j < 16; ++j) {
                float d2 = Ss[t * 16 + j];
                int   i2 = Si[t * 16 + j];
                if (d2 < bd || (d2 == bd && i2 < bi)) { bd = d2; bi = i2; }
            }
            int n = s_n[t];
            g_indices[n] = bi;
            out[(size_t)OFF_IDX + n] = (float)bi;
        }
        __syncthreads();
    }
}

// ---------------------------------------------------------------------------
// Kernel 4: gather z_q, commitment loss, scatter embed_sum, counts
// ---------------------------------------------------------------------------
__global__ void k_gather(const float* __restrict__ z, const float* __restrict__ E,
                         float* __restrict__ out) {
    __shared__ int sidx[64];
    __shared__ float ws[8];
    const int t   = threadIdx.x;   // 256
    const int n0  = blockIdx.x * 64;
    const int b   = n0 >> 10;
    const int rem = n0 & 1023;
    const float* zb = z   + (size_t)b * 262144 + rem;
    float*       qb = out + (size_t)b * 262144 + rem;

    if (t < 64) sidx[t] = g_indices[n0 + t];
    __syncthreads();
    if (t < 64) atomicAdd(&g_counts[sidx[t]], 1.0f);

    float lsum = 0.f;
    #pragma unroll 4
    for (int it = 0; it < 32; ++it) {
        int f  = t + it * 256;
        int d2 = f >> 6, nl = f & 63;
        int d  = d2 << 1;
        int idx = sidx[nl];
        float z0 = zb[d * 1024 + nl];
        float z1 = zb[d * 1024 + 1024 + nl];
        float2 e = *(const float2*)(E + (size_t)idx * 256 + d);
        qb[d * 1024 + nl]        = z0 + (e.x - z0);
        qb[d * 1024 + 1024 + nl] = z1 + (e.y - z1);
        float f0 = z0 - e.x, f1 = z1 - e.y;
        lsum += f0 * f0 + f1 * f1;
        atomicAdd((float2*)(g_embed_sum + (size_t)idx * 256 + d),
                  make_float2(z0, z1));
    }
    #pragma unroll
    for (int o = 16; o; o >>= 1) lsum += __shfl_down_sync(0xffffffffu, lsum, o);
    if ((t & 31) == 0) ws[t >> 5] = lsum;
    __syncthreads();
    if (t == 0) {
        float tot = 0.f;
        #pragma unroll
        for (int i = 0; i < 8; ++i) tot += ws[i];
        atomicAdd(out + OFF_LOSS, tot * (1.0f / 8388608.0f));
    }
}

// ---------------------------------------------------------------------------
// Kernel 5/6: EMA epilogues
// ---------------------------------------------------------------------------
__global__ void k_cs(const float* __restrict__ cs_in, float* __restrict__ out) {
    const int t = threadIdx.x;   // 1024
    float c = 0.99f * cs_in[t] + 0.01f * g_counts[t];
    out[(size_t)OFF_CS + t] = c;

    __shared__ float ws[32];
    __shared__ float n_tot;
    float s = c;
    #pragma unroll
    for (int o = 16; o; o >>= 1) s += __shfl_down_sync(0xffffffffu, s, o);
    if ((t & 31) == 0) ws[t >> 5] = s;
    __syncthreads();
    if (t == 0) {
        float tot = 0.f;
        #pragma unroll
        for (int i = 0; i < 32; ++i) tot += ws[i];
        n_tot = tot;
    }
    __syncthreads();
    float n  = n_tot;
    g_cluster[t] = (c + 1e-5f) / (n + 1024.0f * 1e-5f) * n;
}

__global__ void k_emb(const float* __restrict__ es_in, float* __restrict__ out) {
    const int i = blockIdx.x * 1024 + threadIdx.x;
    float es = 0.99f * es_in[i] + 0.01f * g_embed_sum[i];
    out[(size_t)OFF_ES  + i] = es;
    out[(size_t)OFF_EMB + i] = es / g_cluster[i >> 8];
}

// ---------------------------------------------------------------------------
extern "C" void kernel_launch(void* const* d_in, const int* in_sizes, int n_in,
                              void* d_out, int out_size) {
    const float* z  = (const float*)d_in[0];
    const float* E  = (const float*)d_in[1];
    const float* cs = (const float*)d_in[2];
    const float* es = (const float*)d_in[3];
    float* out = (float*)d_out;

    cudaFuncSetAttribute(k_mma, cudaFuncAttributeMaxDynamicSharedMemorySize,
                         SMEM_MMA_TOTAL);
    cudaFuncSetAttribute(k_exact, cudaFuncAttributeMaxDynamicSharedMemorySize,
                         83456);

    k_init  <<<1024, 256>>>(E, out);
    k_mma   <<< 256, 256, SMEM_MMA_TOTAL>>>(z, out);
    k_exact <<<  64, 128, 83456>>>(z, E, out);
    k_gather<<< 512, 256>>>(z, E, out);
    k_cs    <<<   1, 1024>>>(cs, out);
    k_emb   <<< 256, 1024>>>(es, out);
}

// round 5
// speedup vs baseline: 3.4849x; 3.0623x over previous
#include <cuda_runtime.h>
#include <cuda_fp16.h>
#include <cstdint>

// ---------------------------------------------------------------------------
// VQ-VAE vector quantizer, GB300 sm_103a (sm_103-generic toolchain).
// fp16 mma.sync approximate assign (top-3 candidate tracking) +
// warp-per-row exact candidate rescue + lean gather.
// ---------------------------------------------------------------------------

#define N_ROWS   32768
#define K_CODES  1024
#define D_DIM    256

#define OFF_LOSS 8388608
#define OFF_IDX  8388609
#define OFF_EMB  8421377
#define OFF_CS   8683521
#define OFF_ES   8684545

// contested threshold: covers ref fp32 quantum (ulp(256)~3e-5) + ~40 sigma of
// fp16 GEMM error (sd ~6e-6). Codes within THETA of best are provably inside
// the 24-candidate union (per-thread top-3 over disjoint code partitions).
#define THETA    2.5e-4f

__device__ float   g_enorm[K_CODES];
__device__ int     g_indices[N_ROWS];
__device__ float   g_counts[K_CODES];
__device__ float2  g_embed_sum2[K_CODES * 128];
__device__ float   g_cluster[K_CODES];
__device__ __half  g_E16[K_CODES * D_DIM];
__device__ int     g_cn[N_ROWS];
__device__ int     g_cand[N_ROWS * 24];
__device__ int     g_nc;
__device__ float   g_loss_sc;
__device__ float   g_loss_zn;

// ---------------- helpers --------------------------------------------------
__device__ __forceinline__ uint32_t smem_to_u32(const void* p) {
    uint32_t a;
    asm("{ .reg .u64 t; cvta.to.shared.u64 t, %1; cvt.u32.u64 %0, t; }"
        : "=r"(a) : "l"(p));
    return a;
}

__device__ __forceinline__ void ldm4(uint32_t r[4], uint32_t addr) {
    asm volatile("ldmatrix.sync.aligned.m8n8.x4.shared.b16 {%0,%1,%2,%3}, [%4];"
                 : "=r"(r[0]), "=r"(r[1]), "=r"(r[2]), "=r"(r[3]) : "r"(addr));
}

__device__ __forceinline__ void mma16816(float c[4], const uint32_t a[4],
                                         uint32_t b0, uint32_t b1) {
    asm volatile(
        "mma.sync.aligned.m16n8k16.row.col.f32.f16.f16.f32 "
        "{%0,%1,%2,%3}, {%4,%5,%6,%7}, {%8,%9}, {%0,%1,%2,%3};"
        : "+f"(c[0]), "+f"(c[1]), "+f"(c[2]), "+f"(c[3])
        : "r"(a[0]), "r"(a[1]), "r"(a[2]), "r"(a[3]), "r"(b0), "r"(b1));
}

// ---------------------------------------------------------------------------
// Kernel 1: ||e||^2, E -> fp16, zero scratch
// ---------------------------------------------------------------------------
__global__ void k_init(const float* __restrict__ E, float* __restrict__ out) {
    const int k = blockIdx.x;
    const int t = threadIdx.x;
    float v = E[k * D_DIM + t];
    g_E16[k * D_DIM + t] = __float2half_rn(v);
    float s = v * v;
    #pragma unroll
    for (int o = 16; o; o >>= 1) s += __shfl_down_sync(0xffffffffu, s, o);
    __shared__ float ws[8];
    if ((t & 31) == 0) ws[t >> 5] = s;
    __syncthreads();
    if (t == 0) {
        float tot = 0.f;
        #pragma unroll
        for (int i = 0; i < 8; ++i) tot += ws[i];
        g_enorm[k]  = tot;
        g_counts[k] = 0.f;
        if (k == 0) { g_nc = 0; g_loss_sc = 0.f; g_loss_zn = 0.f; }
    }
    if (t < 128) g_embed_sum2[k * 128 + t] = make_float2(0.f, 0.f);
}

// ---------------------------------------------------------------------------
// Kernel 2: fp16 mma.sync GEMM (128 rows/CTA x 1024 codes, D=256).
// 8 warps: 4(m) x 2(n). Per-thread top-3 per row-slot over its code partition.
// Row reduce merges 8x3 = 24 candidates; gap<THETA -> contested for rescue.
// ---------------------------------------------------------------------------
#define SM_A   0
#define SM_B   65536
#define SM_EN  196608
#define SM_RED SM_B            /* B region reused post-loop for reduction */
#define SMEM_MMA_TOTAL 200704

__global__ __launch_bounds__(256, 1)
void k_mma(const float* __restrict__ z, float* __restrict__ out) {
    extern __shared__ char smem[];
    const uint32_t sb = smem_to_u32(smem);
    const int tid  = threadIdx.x;
    const int warp = tid >> 5;
    const int lane = tid & 31;
    const int n0  = blockIdx.x * 128;
    const int b   = n0 >> 10;
    const int hw0 = n0 & 1023;

    // ---- prologue: A tile (z rows -> fp16, swizzled row-major [row][d]) ----
    const float4* zb4 = (const float4*)(z + (size_t)b * 262144 + hw0);
    #pragma unroll 4
    for (int i = 0; i < 32; ++i) {
        int f  = i * 256 + tid;
        int d  = f >> 5;
        int r4 = f & 31;
        float4 v = zb4[d * 256 + r4];
        float vv[4] = {v.x, v.y, v.z, v.w};
        #pragma unroll
        for (int j = 0; j < 4; ++j) {
            int row = r4 * 4 + j;
            uint32_t off = ((uint32_t)row << 9) | ((uint32_t)d << 1);
            off ^= (uint32_t)(row & 7) << 4;
            *(__half*)(smem + off) = __float2half_rn(vv[j]);
        }
    }
    float* s_en = (float*)(smem + SM_EN);
    #pragma unroll
    for (int i = 0; i < 4; ++i) s_en[tid + i * 256] = g_enorm[tid + i * 256];

    auto issue = [&](int c) {
        const __half* src = g_E16 + (size_t)c * 128 * 256;
        const uint32_t base = sb + SM_B + (uint32_t)(c & 1) * 65536;
        #pragma unroll
        for (int i = 0; i < 16; ++i) {
            int lin  = tid + i * 256;
            int code = lin >> 5, d8 = lin & 31;
            uint32_t off = ((uint32_t)code << 9) + ((uint32_t)d8 << 4);
            off ^= (uint32_t)(code & 7) << 4;
            const void* g = src + code * 256 + d8 * 8;
            asm volatile("cp.async.cg.shared.global [%0], [%1], 16;"
                         :: "r"(base + off), "l"(g));
        }
        asm volatile("cp.async.commit_group;" ::: "memory");
    };
    issue(0);
    issue(1);
    __syncthreads();

    const int mw = warp & 3;
    const int nc = warp >> 2;
    const int mat = lane >> 3, rwi = lane & 7;

    uint32_t aBase[2], aXor[2];
    #pragma unroll
    for (int mt = 0; mt < 2; ++mt) {
        int row = mw * 32 + mt * 16 + rwi + ((mat & 1) << 3);
        aBase[mt] = sb + ((uint32_t)row << 9);
        aXor[mt]  = (uint32_t)(row & 7) << 4;
    }
    const uint32_t aK = (uint32_t)(mat >> 1) << 4;

    uint32_t bBase[4], bXor[4];
    #pragma unroll
    for (int np = 0; np < 4; ++np) {
        int code = nc * 64 + np * 16 + rwi + ((mat >> 1) << 3);
        bBase[np] = ((uint32_t)code << 9);
        bXor[np]  = (uint32_t)(code & 7) << 4;
    }
    const uint32_t bK = (uint32_t)(mat & 1) << 4;

    // per row-slot top-3 over this thread's code partition
    float b1[4], b2[4], b3[4];
    int   i1[4], i2[4], i3[4];
    #pragma unroll
    for (int l = 0; l < 4; ++l) {
        b1[l] = b2[l] = b3[l] = 3.4e38f;
        i1[l] = i2[l] = i3[l] = 0;
    }

    for (int c = 0; c < 8; ++c) {
        if (c == 7) asm volatile("cp.async.wait_group 0;" ::: "memory");
        else        asm volatile("cp.async.wait_group 1;" ::: "memory");
        __syncthreads();

        const uint32_t bBuf = sb + SM_B + (uint32_t)(c & 1) * 65536;
        float acc[2][8][4];
        #pragma unroll
        for (int mt = 0; mt < 2; ++mt)
            #pragma unroll
            for (int nt = 0; nt < 8; ++nt)
                #pragma unroll
                for (int q = 0; q < 4; ++q) acc[mt][nt][q] = 0.f;

        #pragma unroll 2
        for (int ks = 0; ks < 16; ++ks) {
            const uint32_t kb = (uint32_t)ks << 5;
            uint32_t af[2][4], bf[4][4];
            #pragma unroll
            for (int mt = 0; mt < 2; ++mt)
                ldm4(af[mt], aBase[mt] + ((kb + aK) ^ aXor[mt]));
            #pragma unroll
            for (int np = 0; np < 4; ++np)
                ldm4(bf[np], bBuf + bBase[np] + ((kb + bK) ^ bXor[np]));
            #pragma unroll
            for (int mt = 0; mt < 2; ++mt)
                #pragma unroll
                for (int np = 0; np < 4; ++np) {
                    mma16816(acc[mt][np * 2],     af[mt], bf[np][0], bf[np][1]);
                    mma16816(acc[mt][np * 2 + 1], af[mt], bf[np][2], bf[np][3]);
                }
        }

        // fold: sc = enorm - 2*dot, insert into top-3 of row slot
        #pragma unroll
        for (int mt = 0; mt < 2; ++mt)
            #pragma unroll
            for (int nt = 0; nt < 8; ++nt) {
                int code = c * 128 + nc * 64 + nt * 8 + (lane & 3) * 2;
                float en0 = s_en[code], en1 = s_en[code + 1];
                #pragma unroll
                for (int h = 0; h < 2; ++h) {
                    int l = mt * 2 + h;
                    float sc0 = fmaf(-2.0f, acc[mt][nt][h * 2],     en0);
                    float sc1 = fmaf(-2.0f, acc[mt][nt][h * 2 + 1], en1);
                    if (sc0 < b3[l]) {
                        if (sc0 < b1[l]) {
                            b3[l]=b2[l]; i3[l]=i2[l]; b2[l]=b1[l]; i2[l]=i1[l];
                            b1[l]=sc0;   i1[l]=code;
                        } else if (sc0 < b2[l]) {
                            b3[l]=b2[l]; i3[l]=i2[l]; b2[l]=sc0; i2[l]=code;
                        } else { b3[l]=sc0; i3[l]=code; }
                    }
                    if (sc1 < b3[l]) {
                        if (sc1 < b1[l]) {
                            b3[l]=b2[l]; i3[l]=i2[l]; b2[l]=b1[l]; i2[l]=i1[l];
                            b1[l]=sc1;   i1[l]=code + 1;
                        } else if (sc1 < b2[l]) {
                            b3[l]=b2[l]; i3[l]=i2[l]; b2[l]=sc1; i2[l]=code + 1;
                        } else { b3[l]=sc1; i3[l]=code + 1; }
                    }
                }
            }

        __syncthreads();
        if (c + 2 < 8) issue(c + 2);
    }

    // ---- row reduce over 8 partitions x top-3 ----
    __syncthreads();   // all warps done with B region
    float* rb1 = (float*)(smem + SM_RED);
    float* rb2 = (float*)(smem + SM_RED + 4096);
    float* rb3 = (float*)(smem + SM_RED + 8192);
    int*   ri1 = (int*)  (smem + SM_RED + 12288);
    int*   ri2 = (int*)  (smem + SM_RED + 16384);
    int*   ri3 = (int*)  (smem + SM_RED + 20480);
    float* lws = (float*)(smem + SM_RED + 24576);
    const int slot = nc * 4 + (lane & 3);
    #pragma unroll
    for (int l = 0; l < 4; ++l) {
        int R = mw * 32 + (l >> 1) * 16 + (l & 1) * 8 + (lane >> 2);
        rb1[R * 8 + slot] = b1[l]; ri1[R * 8 + slot] = i1[l];
        rb2[R * 8 + slot] = b2[l]; ri2[R * 8 + slot] = i2[l];
        rb3[R * 8 + slot] = b3[l]; ri3[R * 8 + slot] = i3[l];
    }
    __syncthreads();

    float lsum = 0.f;
    if (tid < 128) {
        float B1 = 3.4e38f, B2 = 3.4e38f;
        int I1 = 0x7fffffff;
        #pragma unroll
        for (int s = 0; s < 8; ++s) {
            int base = tid * 8 + s;
            float v; int iv;
            v = rb1[base]; iv = ri1[base];
            if (v < B1 || (v == B1 && iv < I1)) { B2 = B1; B1 = v; I1 = iv; }
            else if (v < B2) B2 = v;
            v = rb2[base]; iv = ri2[base];
            if (v < B1 || (v == B1 && iv < I1)) { B2 = B1; B1 = v; I1 = iv; }
            else if (v < B2) B2 = v;
            v = rb3[base]; iv = ri3[base];
            if (v < B1 || (v == B1 && iv < I1)) { B2 = B1; B1 = v; I1 = iv; }
            else if (v < B2) B2 = v;
        }
        const int n = n0 + tid;
        g_indices[n] = I1;
        out[(size_t)OFF_IDX + n] = (float)I1;
        lsum = B1;
        if (B2 - B1 < THETA) {
            int p = atomicAdd(&g_nc, 1);
            g_cn[p] = n;
            #pragma unroll
            for (int s = 0; s < 8; ++s) {
                int base = tid * 8 + s;
                g_cand[p * 24 + s * 3 + 0] = ri1[base];
                g_cand[p * 24 + s * 3 + 1] = ri2[base];
                g_cand[p * 24 + s * 3 + 2] = ri3[base];
            }
        }
    }
    // block-sum of best scores (loss term)
    #pragma unroll
    for (int o = 16; o; o >>= 1) lsum += __shfl_down_sync(0xffffffffu, lsum, o);
    if (lane == 0) lws[warp] = lsum;
    __syncthreads();
    if (tid == 0) {
        float tot = 0.f;
        #pragma unroll
        for (int i = 0; i < 8; ++i) tot += lws[i];
        atomicAdd(&g_loss_sc, tot);
    }
}

// ---------------------------------------------------------------------------
// Kernel 3: warp-per-row exact rescue over 24 candidates.
// dist = fl(fl(znorm - 2*dot) + enorm); znorm in double rounded once;
// strict-< with lowest-index tie-break (reference semantics).
// ---------------------------------------------------------------------------
__global__ __launch_bounds__(256)
void k_fix(const float* __restrict__ z, const float* __restrict__ E,
           float* __restrict__ out) {
    const int cnt = g_nc;
    const int lane = threadIdx.x & 31;
    const int gw = (blockIdx.x * blockDim.x + threadIdx.x) >> 5;
    const int nw = (gridDim.x * blockDim.x) >> 5;

    for (int r = gw; r < cnt; r += nw) {
        const int n = g_cn[r];
        const int b = n >> 10, pos = n & 1023;
        const float* zr = z + (size_t)b * 262144 + pos;
        float zv[8];
        #pragma unroll
        for (int i = 0; i < 8; ++i)
            zv[i] = zr[(size_t)(lane + 32 * i) * 1024];
        double za = 0.0;
        #pragma unroll
        for (int i = 0; i < 8; ++i) za += (double)zv[i] * zv[i];
        #pragma unroll
        for (int o = 16; o; o >>= 1)
            za += __shfl_xor_sync(0xffffffffu, za, o);
        const float zn = (float)za;

        float bd = 3.4e38f;
        int   bi = 0x7fffffff;
        for (int j = 0; j < 24; ++j) {
            const int k = g_cand[r * 24 + j];
            const float* er = E + (size_t)k * 256 + lane;
            float acc = 0.f;
            #pragma unroll
            for (int i = 0; i < 8; ++i) acc = fmaf(zv[i], er[32 * i], acc);
            #pragma unroll
            for (int o = 16; o; o >>= 1)
                acc += __shfl_xor_sync(0xffffffffu, acc, o);
            float di = (zn - 2.0f * acc) + g_enorm[k];
            if (di < bd || (di == bd && k < bi)) { bd = di; bi = k; }
        }
        if (lane == 0) {
            g_indices[n] = bi;
            out[(size_t)OFF_IDX + n] = (float)bi;
        }
    }
}

// ---------------------------------------------------------------------------
// Kernel 4: gather (z_q_st = E[idx] via smem stage), embed_sum scatter,
// counts, ||z||^2 partial for the loss.
// ---------------------------------------------------------------------------
__global__ __launch_bounds__(256)
void k_gather(const float* __restrict__ z, const float* __restrict__ E,
              float* __restrict__ out) {
    __shared__ float es[32 * 257];
    __shared__ int   sidx[32];
    __shared__ float ws[8];
    const int t   = threadIdx.x;
    const int n0  = blockIdx.x * 32;     // grid 1024
    const int b   = n0 >> 10;
    const int rem = n0 & 1023;

    if (t < 32) sidx[t] = g_indices[n0 + t];
    __syncthreads();
    if (t < 32) atomicAdd(&g_counts[sidx[t]], 1.0f);

    // stage 32 E rows (coalesced)
    #pragma unroll
    for (int k = 0; k < 32; ++k)
        es[k * 257 + t] = E[(size_t)sidx[k] * 256 + t];
    __syncthreads();

    // z_q_st = staged E, written coalesced (d-major layout)
    float* qb = out + (size_t)b * 262144 + rem;
    #pragma unroll 8
    for (int it = 0; it < 32; ++it) {
        int f = t + it * 256;
        int d = f >> 5, nl = f & 31;
        qb[(size_t)d * 1024 + nl] = es[nl * 257 + d];
    }

    // z read (coalesced) -> embed_sum scatter + ||z||^2 partial
    const float* zb = z + (size_t)b * 262144 + rem;
    float zs = 0.f;
    #pragma unroll 4
    for (int it = 0; it < 16; ++it) {
        int f  = t + it * 256;
        int d2 = f >> 5, nl = f & 31;
        float z0 = zb[(size_t)(2 * d2) * 1024 + nl];
        float z1 = zb[(size_t)(2 * d2 + 1) * 1024 + nl];
        zs += z0 * z0 + z1 * z1;
        atomicAdd(&g_embed_sum2[(size_t)sidx[nl] * 128 + d2],
                  make_float2(z0, z1));
    }
    #pragma unroll
    for (int o = 16; o; o >>= 1) zs += __shfl_down_sync(0xffffffffu, zs, o);
    if ((t & 31) == 0) ws[t >> 5] = zs;
    __syncthreads();
    if (t == 0) {
        float tot = 0.f;
        #pragma unroll
        for (int i = 0; i < 8; ++i) tot += ws[i];
        atomicAdd(&g_loss_zn, tot);
    }
}

// ---------------------------------------------------------------------------
// Kernel 5/6: EMA epilogues (+ final loss combine)
// ---------------------------------------------------------------------------
__global__ void k_cs(const float* __restrict__ cs_in, float* __restrict__ out) {
    const int t = threadIdx.x;   // 1024
    float c = 0.99f * cs_in[t] + 0.01f * g_counts[t];
    out[(size_t)OFF_CS + t] = c;

    __shared__ float ws[32];
    __shared__ float n_tot;
    float s = c;
    #pragma unroll
    for (int o = 16; o; o >>= 1) s += __shfl_down_sync(0xffffffffu, s, o);
    if ((t & 31) == 0) ws[t >> 5] = s;
    __syncthreads();
    if (t == 0) {
        float tot = 0.f;
        #pragma unroll
        for (int i = 0; i < 32; ++i) tot += ws[i];
        n_tot = tot;
        out[OFF_LOSS] = (g_loss_zn + g_loss_sc) * (1.0f / 8388608.0f);
    }
    __syncthreads();
    float n = n_tot;
    g_cluster[t] = (c + 1e-5f) / (n + 1024.0f * 1e-5f) * n;
}

__global__ void k_emb(const float* __restrict__ es_in, float* __restrict__ out) {
    const int i = blockIdx.x * 1024 + threadIdx.x;
    float es = 0.99f * es_in[i] + 0.01f * ((const float*)g_embed_sum2)[i];
    out[(size_t)OFF_ES  + i] = es;
    out[(size_t)OFF_EMB + i] = es / g_cluster[i >> 8];
}

// ---------------------------------------------------------------------------
extern "C" void kernel_launch(void* const* d_in, const int* in_sizes, int n_in,
                              void* d_out, int out_size) {
    const float* z  = (const float*)d_in[0];
    const float* E  = (const float*)d_in[1];
    const float* cs = (const float*)d_in[2];
    const float* es = (const float*)d_in[3];
    float* out = (float*)d_out;

    cudaFuncSetAttribute(k_mma, cudaFuncAttributeMaxDynamicSharedMemorySize,
                         SMEM_MMA_TOTAL);

    k_init  <<<1024, 256>>>(E, out);
    k_mma   <<< 256, 256, SMEM_MMA_TOTAL>>>(z, out);
    k_fix   <<< 128, 256>>>(z, E, out);
    k_gather<<<1024, 256>>>(z, E, out);
    k_cs    <<<   1, 1024>>>(cs, out);
    k_emb   <<< 256, 1024>>>(es, out);
}

// round 6
// speedup vs baseline: 3.9147x; 1.1233x over previous
#include <cuda_runtime.h>
#include <cuda_fp16.h>
#include <cstdint>

// ---------------------------------------------------------------------------
// VQ-VAE vector quantizer, GB300 sm_103a (sm_103-generic toolchain).
// fp16 mma.sync approximate assign (top-3 candidates) + warp-per-row exact
// rescue + fused gather/scatter + merged EMA epilogue.
// ---------------------------------------------------------------------------

#define N_ROWS   32768
#define K_CODES  1024
#define D_DIM    256

#define OFF_LOSS 8388608
#define OFF_IDX  8388609
#define OFF_EMB  8421377
#define OFF_CS   8683521
#define OFF_ES   8684545

#define THETA    2.5e-4f

__device__ float   g_enorm[K_CODES];
__device__ int     g_indices[N_ROWS];
__device__ float   g_counts[K_CODES];
__device__ float4  g_embed_sum4[K_CODES * 64];
__device__ __half  g_E16[K_CODES * D_DIM];
__device__ int     g_cn[N_ROWS];
__device__ int     g_cand[N_ROWS * 24];
__device__ int     g_nc;
__device__ float   g_loss_sc;
__device__ float   g_loss_zn;

// ---------------- helpers --------------------------------------------------
__device__ __forceinline__ uint32_t smem_to_u32(const void* p) {
    uint32_t a;
    asm("{ .reg .u64 t; cvta.to.shared.u64 t, %1; cvt.u32.u64 %0, t; }"
        : "=r"(a) : "l"(p));
    return a;
}

__device__ __forceinline__ void ldm4(uint32_t r[4], uint32_t addr) {
    asm volatile("ldmatrix.sync.aligned.m8n8.x4.shared.b16 {%0,%1,%2,%3}, [%4];"
                 : "=r"(r[0]), "=r"(r[1]), "=r"(r[2]), "=r"(r[3]) : "r"(addr));
}

__device__ __forceinline__ void mma16816(float c[4], const uint32_t a[4],
                                         uint32_t b0, uint32_t b1) {
    asm volatile(
        "mma.sync.aligned.m16n8k16.row.col.f32.f16.f16.f32 "
        "{%0,%1,%2,%3}, {%4,%5,%6,%7}, {%8,%9}, {%0,%1,%2,%3};"
        : "+f"(c[0]), "+f"(c[1]), "+f"(c[2]), "+f"(c[3])
        : "r"(a[0]), "r"(a[1]), "r"(a[2]), "r"(a[3]), "r"(b0), "r"(b1));
}

// ---------------------------------------------------------------------------
// Kernel 1: ||e||^2, E -> fp16, zero scratch
// ---------------------------------------------------------------------------
__global__ void k_init(const float* __restrict__ E, float* __restrict__ out) {
    const int k = blockIdx.x;
    const int t = threadIdx.x;
    float v = E[k * D_DIM + t];
    g_E16[k * D_DIM + t] = __float2half_rn(v);
    float s = v * v;
    #pragma unroll
    for (int o = 16; o; o >>= 1) s += __shfl_down_sync(0xffffffffu, s, o);
    __shared__ float ws[8];
    if ((t & 31) == 0) ws[t >> 5] = s;
    __syncthreads();
    if (t == 0) {
        float tot = 0.f;
        #pragma unroll
        for (int i = 0; i < 8; ++i) tot += ws[i];
        g_enorm[k]  = tot;
        g_counts[k] = 0.f;
        if (k == 0) { g_nc = 0; g_loss_sc = 0.f; g_loss_zn = 0.f; }
    }
    ((float*)g_embed_sum4)[k * 256 + t] = 0.f;
}

// ---------------------------------------------------------------------------
// Kernel 2: fp16 mma.sync GEMM (128 rows/CTA x 1024 codes, D=256).
// 8 warps: 4(m) x 2(n). Per-thread top-3 per row-slot over its code partition.
// Row reduce merges 8x3 = 24 candidates; gap<THETA -> contested for rescue.
// ---------------------------------------------------------------------------
#define SM_A   0
#define SM_B   65536
#define SM_EN  196608
#define SM_RED SM_B            /* B region reused post-loop for reduction */
#define SMEM_MMA_TOTAL 200704

__global__ __launch_bounds__(256, 1)
void k_mma(const float* __restrict__ z, float* __restrict__ out) {
    extern __shared__ char smem[];
    const uint32_t sb = smem_to_u32(smem);
    const int tid  = threadIdx.x;
    const int warp = tid >> 5;
    const int lane = tid & 31;
    const int n0  = blockIdx.x * 128;
    const int b   = n0 >> 10;
    const int hw0 = n0 & 1023;

    // ---- prologue: A tile (z rows -> fp16, swizzled row-major [row][d]) ----
    // each iter handles a d-pair for 4 rows -> half2 stores
    const float4* zb4 = (const float4*)(z + (size_t)b * 262144 + hw0);
    #pragma unroll 4
    for (int i = 0; i < 16; ++i) {
        int f  = i * 256 + tid;
        int d2 = f >> 5;           // 0..127 (pair 2*d2, 2*d2+1)
        int r4 = f & 31;
        float4 v0 = zb4[(2 * d2) * 256 + r4];
        float4 v1 = zb4[(2 * d2 + 1) * 256 + r4];
        float a0[4] = {v0.x, v0.y, v0.z, v0.w};
        float a1[4] = {v1.x, v1.y, v1.z, v1.w};
        #pragma unroll
        for (int j = 0; j < 4; ++j) {
            int row = r4 * 4 + j;
            uint32_t off = ((uint32_t)row << 9) | ((uint32_t)d2 << 2);
            off ^= (uint32_t)(row & 7) << 4;
            *(__half2*)(smem + off) = __floats2half2_rn(a0[j], a1[j]);
        }
    }
    float* s_en = (float*)(smem + SM_EN);
    #pragma unroll
    for (int i = 0; i < 4; ++i) s_en[tid + i * 256] = g_enorm[tid + i * 256];

    auto issue = [&](int c) {
        const __half* src = g_E16 + (size_t)c * 128 * 256;
        const uint32_t base = sb + SM_B + (uint32_t)(c & 1) * 65536;
        #pragma unroll
        for (int i = 0; i < 16; ++i) {
            int lin  = tid + i * 256;
            int code = lin >> 5, d8 = lin & 31;
            uint32_t off = ((uint32_t)code << 9) + ((uint32_t)d8 << 4);
            off ^= (uint32_t)(code & 7) << 4;
            const void* g = src + code * 256 + d8 * 8;
            asm volatile("cp.async.cg.shared.global [%0], [%1], 16;"
                         :: "r"(base + off), "l"(g));
        }
        asm volatile("cp.async.commit_group;" ::: "memory");
    };
    issue(0);
    issue(1);
    __syncthreads();

    const int mw = warp & 3;
    const int nc = warp >> 2;
    const int mat = lane >> 3, rwi = lane & 7;

    uint32_t aBase[2], aXor[2];
    #pragma unroll
    for (int mt = 0; mt < 2; ++mt) {
        int row = mw * 32 + mt * 16 + rwi + ((mat & 1) << 3);
        aBase[mt] = sb + ((uint32_t)row << 9);
        aXor[mt]  = (uint32_t)(row & 7) << 4;
    }
    const uint32_t aK = (uint32_t)(mat >> 1) << 4;

    uint32_t bBase[4], bXor[4];
    #pragma unroll
    for (int np = 0; np < 4; ++np) {
        int code = nc * 64 + np * 16 + rwi + ((mat >> 1) << 3);
        bBase[np] = ((uint32_t)code << 9);
        bXor[np]  = (uint32_t)(code & 7) << 4;
    }
    const uint32_t bK = (uint32_t)(mat & 1) << 4;

    float b1[4], b2[4], b3[4];
    int   i1[4], i2[4], i3[4];
    #pragma unroll
    for (int l = 0; l < 4; ++l) {
        b1[l] = b2[l] = b3[l] = 3.4e38f;
        i1[l] = i2[l] = i3[l] = 0;
    }

    for (int c = 0; c < 8; ++c) {
        if (c == 7) asm volatile("cp.async.wait_group 0;" ::: "memory");
        else        asm volatile("cp.async.wait_group 1;" ::: "memory");
        __syncthreads();

        const uint32_t bBuf = sb + SM_B + (uint32_t)(c & 1) * 65536;
        float acc[2][8][4];
        #pragma unroll
        for (int mt = 0; mt < 2; ++mt)
            #pragma unroll
            for (int nt = 0; nt < 8; ++nt)
                #pragma unroll
                for (int q = 0; q < 4; ++q) acc[mt][nt][q] = 0.f;

        #pragma unroll 2
        for (int ks = 0; ks < 16; ++ks) {
            const uint32_t kb = (uint32_t)ks << 5;
            uint32_t af[2][4], bf[4][4];
            #pragma unroll
            for (int mt = 0; mt < 2; ++mt)
                ldm4(af[mt], aBase[mt] + ((kb + aK) ^ aXor[mt]));
            #pragma unroll
            for (int np = 0; np < 4; ++np)
                ldm4(bf[np], bBuf + bBase[np] + ((kb + bK) ^ bXor[np]));
            #pragma unroll
            for (int mt = 0; mt < 2; ++mt)
                #pragma unroll
                for (int np = 0; np < 4; ++np) {
                    mma16816(acc[mt][np * 2],     af[mt], bf[np][0], bf[np][1]);
                    mma16816(acc[mt][np * 2 + 1], af[mt], bf[np][2], bf[np][3]);
                }
        }

        #pragma unroll
        for (int mt = 0; mt < 2; ++mt)
            #pragma unroll
            for (int nt = 0; nt < 8; ++nt) {
                int code = c * 128 + nc * 64 + nt * 8 + (lane & 3) * 2;
                float en0 = s_en[code], en1 = s_en[code + 1];
                #pragma unroll
                for (int h = 0; h < 2; ++h) {
                    int l = mt * 2 + h;
                    float sc0 = fmaf(-2.0f, acc[mt][nt][h * 2],     en0);
                    float sc1 = fmaf(-2.0f, acc[mt][nt][h * 2 + 1], en1);
                    if (sc0 < b3[l]) {
                        if (sc0 < b1[l]) {
                            b3[l]=b2[l]; i3[l]=i2[l]; b2[l]=b1[l]; i2[l]=i1[l];
                            b1[l]=sc0;   i1[l]=code;
                        } else if (sc0 < b2[l]) {
                            b3[l]=b2[l]; i3[l]=i2[l]; b2[l]=sc0; i2[l]=code;
                        } else { b3[l]=sc0; i3[l]=code; }
                    }
                    if (sc1 < b3[l]) {
                        if (sc1 < b1[l]) {
                            b3[l]=b2[l]; i3[l]=i2[l]; b2[l]=b1[l]; i2[l]=i1[l];
                            b1[l]=sc1;   i1[l]=code + 1;
                        } else if (sc1 < b2[l]) {
                            b3[l]=b2[l]; i3[l]=i2[l]; b2[l]=sc1; i2[l]=code + 1;
                        } else { b3[l]=sc1; i3[l]=code + 1; }
                    }
                }
            }

        __syncthreads();
        if (c + 2 < 8) issue(c + 2);
    }

    // ---- row reduce over 8 partitions x top-3 ----
    __syncthreads();
    float* rb1 = (float*)(smem + SM_RED);
    float* rb2 = (float*)(smem + SM_RED + 4096);
    float* rb3 = (float*)(smem + SM_RED + 8192);
    int*   ri1 = (int*)  (smem + SM_RED + 12288);
    int*   ri2 = (int*)  (smem + SM_RED + 16384);
    int*   ri3 = (int*)  (smem + SM_RED + 20480);
    float* lws = (float*)(smem + SM_RED + 24576);
    const int slot = nc * 4 + (lane & 3);
    #pragma unroll
    for (int l = 0; l < 4; ++l) {
        int R = mw * 32 + (l >> 1) * 16 + (l & 1) * 8 + (lane >> 2);
        rb1[R * 8 + slot] = b1[l]; ri1[R * 8 + slot] = i1[l];
        rb2[R * 8 + slot] = b2[l]; ri2[R * 8 + slot] = i2[l];
        rb3[R * 8 + slot] = b3[l]; ri3[R * 8 + slot] = i3[l];
    }
    __syncthreads();

    float lsum = 0.f;
    if (tid < 128) {
        float B1 = 3.4e38f, B2 = 3.4e38f;
        int I1 = 0x7fffffff;
        #pragma unroll
        for (int s = 0; s < 8; ++s) {
            int base = tid * 8 + s;
            float v; int iv;
            v = rb1[base]; iv = ri1[base];
            if (v < B1 || (v == B1 && iv < I1)) { B2 = B1; B1 = v; I1 = iv; }
            else if (v < B2) B2 = v;
            v = rb2[base]; iv = ri2[base];
            if (v < B1 || (v == B1 && iv < I1)) { B2 = B1; B1 = v; I1 = iv; }
            else if (v < B2) B2 = v;
            v = rb3[base]; iv = ri3[base];
            if (v < B1 || (v == B1 && iv < I1)) { B2 = B1; B1 = v; I1 = iv; }
            else if (v < B2) B2 = v;
        }
        const int n = n0 + tid;
        g_indices[n] = I1;
        out[(size_t)OFF_IDX + n] = (float)I1;
        lsum = B1;
        if (B2 - B1 < THETA) {
            int p = atomicAdd(&g_nc, 1);
            g_cn[p] = n;
            #pragma unroll
            for (int s = 0; s < 8; ++s) {
                int base = tid * 8 + s;
                g_cand[p * 24 + s * 3 + 0] = ri1[base];
                g_cand[p * 24 + s * 3 + 1] = ri2[base];
                g_cand[p * 24 + s * 3 + 2] = ri3[base];
            }
        }
    }
    #pragma unroll
    for (int o = 16; o; o >>= 1) lsum += __shfl_down_sync(0xffffffffu, lsum, o);
    if (lane == 0) lws[warp] = lsum;
    __syncthreads();
    if (tid == 0) {
        float tot = 0.f;
        #pragma unroll
        for (int i = 0; i < 8; ++i) tot += lws[i];
        atomicAdd(&g_loss_sc, tot);
    }
}

// ---------------------------------------------------------------------------
// Kernel 3: warp-per-row exact rescue over 24 candidates (4-wide batches).
// dist = fl(fl(znorm - 2*dot) + enorm); znorm in double rounded once;
// strict-< with lowest-index tie-break (reference semantics).
// ---------------------------------------------------------------------------
__global__ __launch_bounds__(256)
void k_fix(const float* __restrict__ z, const float* __restrict__ E,
           float* __restrict__ out) {
    const int cnt = g_nc;
    const int lane = threadIdx.x & 31;
    const int gw = (blockIdx.x * blockDim.x + threadIdx.x) >> 5;
    const int nw = (gridDim.x * blockDim.x) >> 5;

    for (int r = gw; r < cnt; r += nw) {
        const int n = g_cn[r];
        const int b = n >> 10, pos = n & 1023;
        const float* zr = z + (size_t)b * 262144 + pos;
        float zv[8];
        #pragma unroll
        for (int i = 0; i < 8; ++i)
            zv[i] = zr[(size_t)(lane + 32 * i) * 1024];
        double za = 0.0;
        #pragma unroll
        for (int i = 0; i < 8; ++i) za += (double)zv[i] * zv[i];
        #pragma unroll
        for (int o = 16; o; o >>= 1)
            za += __shfl_xor_sync(0xffffffffu, za, o);
        const float zn = (float)za;

        float bd = 3.4e38f;
        int   bi = 0x7fffffff;
        #pragma unroll 1
        for (int jb = 0; jb < 24; jb += 4) {
            int kc[4];
            float ac[4] = {0.f, 0.f, 0.f, 0.f};
            #pragma unroll
            for (int q = 0; q < 4; ++q) kc[q] = g_cand[r * 24 + jb + q];
            #pragma unroll
            for (int i = 0; i < 8; ++i) {
                #pragma unroll
                for (int q = 0; q < 4; ++q)
                    ac[q] = fmaf(zv[i], E[(size_t)kc[q] * 256 + lane + 32 * i],
                                 ac[q]);
            }
            #pragma unroll
            for (int o = 16; o; o >>= 1) {
                #pragma unroll
                for (int q = 0; q < 4; ++q)
                    ac[q] += __shfl_xor_sync(0xffffffffu, ac[q], o);
            }
            #pragma unroll
            for (int q = 0; q < 4; ++q) {
                float di = (zn - 2.0f * ac[q]) + g_enorm[kc[q]];
                if (di < bd || (di == bd && kc[q] < bi)) { bd = di; bi = kc[q]; }
            }
        }
        if (lane == 0) {
            g_indices[n] = bi;
            out[(size_t)OFF_IDX + n] = (float)bi;
        }
    }
}

// ---------------------------------------------------------------------------
// Kernel 4: fused gather/scatter. z_q_st = fl(z + fl(E[idx]-z)) (reference
// rounding), ||z||^2 partial, float4 RED scatter into embed_sum, counts.
// ---------------------------------------------------------------------------
__global__ __launch_bounds__(256)
void k_gather(const float* __restrict__ z, const float* __restrict__ E,
              float* __restrict__ out) {
    __shared__ float es[32 * 260];
    __shared__ int   sidx[32];
    __shared__ float ws[8];
    const int t   = threadIdx.x;
    const int n0  = blockIdx.x * 32;     // grid 1024
    const int b   = n0 >> 10;
    const int rem = n0 & 1023;

    if (t < 32) {
        int k = g_indices[n0 + t];
        sidx[t] = k;
        atomicAdd(&g_counts[k], 1.0f);
    }
    __syncthreads();

    #pragma unroll
    for (int k = 0; k < 32; ++k)
        es[k * 260 + t] = E[(size_t)sidx[k] * 256 + t];
    __syncthreads();

    const float* zb = z   + (size_t)b * 262144 + rem;
    float*       qb = out + (size_t)b * 262144 + rem;

    float zs = 0.f;
    #pragma unroll 2
    for (int it = 0; it < 8; ++it) {
        int idx = t + it * 256;          // 0..2047
        int nl  = idx & 31;
        int d4  = idx >> 5;              // 0..63
        int d   = d4 << 2;
        float4 e = *(const float4*)&es[nl * 260 + d];
        float z0 = zb[(size_t)(d + 0) * 1024 + nl];
        float z1 = zb[(size_t)(d + 1) * 1024 + nl];
        float z2 = zb[(size_t)(d + 2) * 1024 + nl];
        float z3 = zb[(size_t)(d + 3) * 1024 + nl];
        qb[(size_t)(d + 0) * 1024 + nl] = z0 + (e.x - z0);
        qb[(size_t)(d + 1) * 1024 + nl] = z1 + (e.y - z1);
        qb[(size_t)(d + 2) * 1024 + nl] = z2 + (e.z - z2);
        qb[(size_t)(d + 3) * 1024 + nl] = z3 + (e.w - z3);
        zs += z0 * z0 + z1 * z1 + z2 * z2 + z3 * z3;
        atomicAdd(&g_embed_sum4[(size_t)sidx[nl] * 64 + d4],
                  make_float4(z0, z1, z2, z3));
    }
    #pragma unroll
    for (int o = 16; o; o >>= 1) zs += __shfl_down_sync(0xffffffffu, zs, o);
    if ((t & 31) == 0) ws[t >> 5] = zs;
    __syncthreads();
    if (t == 0) {
        float tot = 0.f;
        #pragma unroll
        for (int i = 0; i < 8; ++i) tot += ws[i];
        atomicAdd(&g_loss_zn, tot);
    }
}

// ---------------------------------------------------------------------------
// Kernel 5: merged EMA epilogue. n = 0.99*sum(cs_in) + 0.01*32768 (counts sum
// to N_ROWS exactly). Writes new_cs, new_es, new_embedding, loss.
// ---------------------------------------------------------------------------
__global__ __launch_bounds__(1024)
void k_emb(const float* __restrict__ cs_in, const float* __restrict__ es_in,
           float* __restrict__ out) {
    __shared__ float s_n;
    const int tid = threadIdx.x;
    const int i = blockIdx.x * 1024 + tid;   // grid 256 -> 262144

    if (tid < 32) {
        float s = 0.f;
        #pragma unroll
        for (int j = 0; j < 32; ++j) s += cs_in[tid + j * 32];
        #pragma unroll
        for (int o = 16; o; o >>= 1) s += __shfl_xor_sync(0xffffffffu, s, o);
        if (tid == 0) s_n = 0.99f * s + 327.68f;
    }
    __syncthreads();

    const int k = i >> 8;
    float c = 0.99f * cs_in[k] + 0.01f * g_counts[k];
    if ((i & 255) == 0) out[(size_t)OFF_CS + k] = c;
    float n  = s_n;
    float cl = (c + 1e-5f) / (n + 0.01024f) * n;
    float es = 0.99f * es_in[i] + 0.01f * ((const float*)g_embed_sum4)[i];
    out[(size_t)OFF_ES  + i] = es;
    out[(size_t)OFF_EMB + i] = es / cl;
    if (i == 0)
        out[OFF_LOSS] = (g_loss_zn + g_loss_sc) * (1.0f / 8388608.0f);
}

// ---------------------------------------------------------------------------
extern "C" void kernel_launch(void* const* d_in, const int* in_sizes, int n_in,
                              void* d_out, int out_size) {
    const float* z  = (const float*)d_in[0];
    const float* E  = (const float*)d_in[1];
    const float* cs = (const float*)d_in[2];
    const float* es = (const float*)d_in[3];
    float* out = (float*)d_out;

    cudaFuncSetAttribute(k_mma, cudaFuncAttributeMaxDynamicSharedMemorySize,
                         SMEM_MMA_TOTAL);

    k_init  <<<1024, 256>>>(E, out);
    k_mma   <<< 256, 256, SMEM_MMA_TOTAL>>>(z, out);
    k_fix   <<< 128, 256>>>(z, E, out);
    k_gather<<<1024, 256>>>(z, E, out);
    k_emb   <<< 256, 1024>>>(cs, es, out);
}